// round 1
// baseline (speedup 1.0000x reference)
#include <cuda_runtime.h>

// Problem constants (fixed by setup_inputs)
#define Bb    2
#define Tt    2048
#define Cc    1024
#define QLd   128
#define KVL   128
#define NHh   16
#define HSd   64
#define BT    (Bb*Tt)          // 4096

// Scratch (device globals: no allocation allowed)
__device__ float g_P [QLd*KVL];          // W_uq^T @ W_uk            (128,128)
__device__ float g_M [Cc*KVL];           // W_dq^T @ P               (1024,128)
__device__ float g_N [NHh*QLd*KVL];      // per-head absorbed K      (16,128,128)
__device__ float g_R [Cc*KVL];           // W_o @ W_uv               (1024,128)
__device__ float g_Aq[BT*QLd];           // x @ W_dq^T               (4096,128)
__device__ float g_ql[NHh*BT*KVL];       // per-head latent queries  (16,4096,128)
__device__ float g_ct[NHh*BT*KVL];       // per-head latent context  (16,4096,128)

// ---------------------------------------------------------------------------
// Generic tiled GEMM. MODE: 0 = NN (A[M,K], B[K,N]), 1 = NT (A[M,K], B[N,K]),
// 2 = TN (A[K,M], B[K,N]).  C[m*ldc + n] = sum_k opA*opB.  Batched via grid.z.
// ---------------------------------------------------------------------------
template<int MODE>
__global__ __launch_bounds__(256)
void gemm_kernel(const float* __restrict__ A, const float* __restrict__ B,
                 float* __restrict__ C, int M, int N, int K, int ldc,
                 long sA, long sB, long sC)
{
    constexpr int BM = 64, BN = 64, BK = 16;
    __shared__ float As[BK][BM + 1];
    __shared__ float Bs[BK][BN + 1];

    const int bz = blockIdx.z;
    A += (long)bz * sA;  B += (long)bz * sB;  C += (long)bz * sC;

    const int m0 = blockIdx.x * BM, n0 = blockIdx.y * BN;
    const int t  = threadIdx.x;
    const int ty = t >> 4, tx = t & 15;

    float acc[4][4] = {};

    for (int k0 = 0; k0 < K; k0 += BK) {
        #pragma unroll
        for (int i = 0; i < 4; i++) {
            int idx = t + i * 256;
            if (MODE == 2) {                  // A[K,M], m contiguous
                int am = idx & 63, ak = idx >> 6;
                As[ak][am] = A[(long)(k0 + ak) * M + m0 + am];
            } else {                          // A[M,K], k contiguous
                int ak = idx & 15, am = idx >> 4;
                As[ak][am] = A[(long)(m0 + am) * K + k0 + ak];
            }
        }
        #pragma unroll
        for (int i = 0; i < 4; i++) {
            int idx = t + i * 256;
            if (MODE == 1) {                  // B[N,K], k contiguous
                int bk = idx & 15, bn = idx >> 4;
                Bs[bk][bn] = B[(long)(n0 + bn) * K + k0 + bk];
            } else {                          // B[K,N], n contiguous
                int bn = idx & 63, bk = idx >> 6;
                Bs[bk][bn] = B[(long)(k0 + bk) * N + n0 + bn];
            }
        }
        __syncthreads();

        #pragma unroll
        for (int kk = 0; kk < BK; kk++) {
            float a[4], b[4];
            #pragma unroll
            for (int i = 0; i < 4; i++) a[i] = As[kk][ty * 4 + i];
            #pragma unroll
            for (int j = 0; j < 4; j++) b[j] = Bs[kk][tx * 4 + j];
            #pragma unroll
            for (int i = 0; i < 4; i++)
                #pragma unroll
                for (int j = 0; j < 4; j++) acc[i][j] += a[i] * b[j];
        }
        __syncthreads();
    }

    #pragma unroll
    for (int i = 0; i < 4; i++)
        #pragma unroll
        for (int j = 0; j < 4; j++)
            C[(long)(m0 + ty * 4 + i) * ldc + n0 + tx * 4 + j] = acc[i][j];
}

// ---------------------------------------------------------------------------
// Flash attention over latent space. Per (b,h): Q = ql[h] (T,128),
// K = V = ckv (T,128). Causal, scale 1/sqrt(64). Output ctx (T,128).
// 64-query x 64-key tiles, 256 threads; thread (ty,tx): S tile rows ty*4..+3,
// S cols tx*4..+3, O cols tx*8..+7. Smem d-major padded layouts.
// ---------------------------------------------------------------------------
#define APAD 66
#define SMEM_FLOATS (2 * 128 * APAD + 64 * 65)

__global__ __launch_bounds__(256)
void attn_kernel(const float* __restrict__ ql, const float* __restrict__ ckv,
                 float* __restrict__ ctx)
{
    extern __shared__ float sm[];
    float* Qs = sm;                    // [128][APAD]  (d-major, rows padded)
    float* Ks = sm + 128 * APAD;       // [128][APAD]
    float* Ps = sm + 2 * 128 * APAD;   // [64][65]     (s-major over rows)

    const int qt = blockIdx.x;               // query tile 0..31
    const int bh = blockIdx.y;               // 0..31
    const int b  = bh >> 4, h = bh & 15;
    const int t  = threadIdx.x;
    const int ty = t >> 4, tx = t & 15;
    const int r0 = ty * 4, c0 = tx * 4, oc0 = tx * 8;

    const long qbase = ((long)h * BT + (long)b * Tt + qt * 64) * KVL;
    const long kbase = (long)b * Tt * KVL;

    for (int idx = t; idx < 64 * 128; idx += 256) {
        int r = idx >> 7, d = idx & 127;
        Qs[d * APAD + r] = ql[qbase + (long)r * KVL + d];
    }

    float m[4], l[4], acc[4][8];
    #pragma unroll
    for (int i = 0; i < 4; i++) {
        m[i] = -1e30f; l[i] = 0.f;
        #pragma unroll
        for (int j = 0; j < 8; j++) acc[i][j] = 0.f;
    }

    for (int kt = 0; kt <= qt; kt++) {
        __syncthreads();    // prior O-phase done before Ks overwrite (also covers Qs)
        for (int idx = t; idx < 64 * 128; idx += 256) {
            int s = idx >> 7, d = idx & 127;
            Ks[d * APAD + s] = ckv[kbase + (long)(kt * 64 + s) * KVL + d];
        }
        __syncthreads();

        // S = Q K^T / 8
        float S[4][4] = {};
        for (int d = 0; d < 128; d++) {
            float qa[4], kb[4];
            #pragma unroll
            for (int i = 0; i < 4; i++) qa[i] = Qs[d * APAD + r0 + i];
            #pragma unroll
            for (int j = 0; j < 4; j++) kb[j] = Ks[d * APAD + c0 + j];
            #pragma unroll
            for (int i = 0; i < 4; i++)
                #pragma unroll
                for (int j = 0; j < 4; j++) S[i][j] += qa[i] * kb[j];
        }
        #pragma unroll
        for (int i = 0; i < 4; i++)
            #pragma unroll
            for (int j = 0; j < 4; j++) {
                S[i][j] *= 0.125f;
                if (kt == qt && (c0 + j) > (r0 + i)) S[i][j] = -1e30f;
            }

        // online softmax (row stats replicated across the 16 tx of each ty)
        #pragma unroll
        for (int i = 0; i < 4; i++) {
            float mt = fmaxf(fmaxf(S[i][0], S[i][1]), fmaxf(S[i][2], S[i][3]));
            #pragma unroll
            for (int o = 1; o < 16; o <<= 1)
                mt = fmaxf(mt, __shfl_xor_sync(0xffffffffu, mt, o));
            float mn = fmaxf(m[i], mt);
            float sc = __expf(m[i] - mn);
            float ls = 0.f;
            #pragma unroll
            for (int j = 0; j < 4; j++) {
                float p = __expf(S[i][j] - mn);
                S[i][j] = p;  ls += p;
            }
            #pragma unroll
            for (int o = 1; o < 16; o <<= 1)
                ls += __shfl_xor_sync(0xffffffffu, ls, o);
            l[i] = l[i] * sc + ls;
            m[i] = mn;
            #pragma unroll
            for (int j = 0; j < 8; j++) acc[i][j] *= sc;
        }

        #pragma unroll
        for (int i = 0; i < 4; i++)
            #pragma unroll
            for (int j = 0; j < 4; j++)
                Ps[(c0 + j) * 65 + r0 + i] = S[i][j];
        __syncthreads();

        // O += P @ Ktile   (Ktile[s][d] = Ks[d][s])
        for (int s = 0; s < 64; s++) {
            float pv[4], kv[8];
            #pragma unroll
            for (int i = 0; i < 4; i++) pv[i] = Ps[s * 65 + r0 + i];
            #pragma unroll
            for (int j = 0; j < 8; j++) kv[j] = Ks[(oc0 + j) * APAD + s];
            #pragma unroll
            for (int i = 0; i < 4; i++)
                #pragma unroll
                for (int j = 0; j < 8; j++) acc[i][j] += pv[i] * kv[j];
        }
    }

    #pragma unroll
    for (int i = 0; i < 4; i++) {
        float inv = 1.f / l[i];
        #pragma unroll
        for (int j = 0; j < 8; j++)
            ctx[qbase + (long)(r0 + i) * KVL + oc0 + j] = acc[i][j] * inv;
    }
}

// ---------------------------------------------------------------------------
extern "C" void kernel_launch(void* const* d_in, const int* in_sizes, int n_in,
                              void* d_out, int out_size)
{
    const float* x     = (const float*)d_in[0];
    const float* W_dq  = (const float*)d_in[1];
    const float* W_uq  = (const float*)d_in[2];
    const float* W_dkv = (const float*)d_in[3];
    const float* W_uk  = (const float*)d_in[4];
    const float* W_uv  = (const float*)d_in[5];
    const float* W_o   = (const float*)d_in[6];

    float* y   = (float*)d_out;              // (B,T,C) = 4194304 floats
    float* ckv = y + (long)BT * Cc;          // (B,T,128)

    float *P, *Mm, *Nw, *R, *Aq, *QLp, *CT;
    cudaGetSymbolAddress((void**)&P,  g_P);
    cudaGetSymbolAddress((void**)&Mm, g_M);
    cudaGetSymbolAddress((void**)&Nw, g_N);
    cudaGetSymbolAddress((void**)&R,  g_R);
    cudaGetSymbolAddress((void**)&Aq, g_Aq);
    cudaGetSymbolAddress((void**)&QLp, g_ql);
    cudaGetSymbolAddress((void**)&CT, g_ct);

    dim3 blk(256);

    // P = W_uq^T @ W_uk                       (128,128,K=1024)  TN
    gemm_kernel<2><<<dim3(2, 2, 1), blk>>>(W_uq, W_uk, P, 128, 128, 1024, 128, 0, 0, 0);
    // M = W_dq^T @ P                          (1024,128,K=128)  TN
    gemm_kernel<2><<<dim3(16, 2, 1), blk>>>(W_dq, P, Mm, 1024, 128, 128, 128, 0, 0, 0);
    // N[h] = W_uq[h*64:,:]^T @ M[h*64:,:]     (128,128,K=64)    TN, batch 16
    gemm_kernel<2><<<dim3(2, 2, 16), blk>>>(W_uq, Mm, Nw, 128, 128, 64, 128,
                                            64 * 128, 64 * 128, 128 * 128);
    // R = W_o @ W_uv                          (1024,128,K=1024) NN
    gemm_kernel<0><<<dim3(16, 2, 1), blk>>>(W_o, W_uv, R, 1024, 128, 1024, 128, 0, 0, 0);
    // Aq = x @ W_dq^T                         (4096,128,K=1024) NT
    gemm_kernel<1><<<dim3(64, 2, 1), blk>>>(x, W_dq, Aq, BT, 128, 1024, 128, 0, 0, 0);
    // ckv = x @ W_dkv^T  -> second output     (4096,128,K=1024) NT
    gemm_kernel<1><<<dim3(64, 2, 1), blk>>>(x, W_dkv, ckv, BT, 128, 1024, 128, 0, 0, 0);
    // ql[h] = Aq @ N[h]                       (4096,128,K=128)  NN, batch 16
    gemm_kernel<0><<<dim3(64, 2, 16), blk>>>(Aq, Nw, QLp, BT, 128, 128, 128,
                                             0, 128 * 128, (long)BT * 128);

    // flash attention over latent space -> ctx
    size_t smem = SMEM_FLOATS * sizeof(float);
    cudaFuncSetAttribute(attn_kernel, cudaFuncAttributeMaxDynamicSharedMemorySize, (int)smem);
    attn_kernel<<<dim3(32, 32, 1), blk, smem>>>(QLp, ckv, CT);

    // y[:, h*64+d] = ctx[h] @ R[h*64+d,:]^T   (4096,64,K=128)   NT, batch 16
    gemm_kernel<1><<<dim3(64, 1, 16), blk>>>(CT, R, y, BT, 64, 128, 1024,
                                             (long)BT * 128, 64 * 128, 64);
}

// round 3
// speedup vs baseline: 3.7452x; 3.7452x over previous
#include <cuda_runtime.h>
#include <cstdint>

// Problem constants (fixed by setup_inputs)
#define Bb    2
#define Tt    2048
#define Cc    1024
#define QLd   128
#define KVL   128
#define NHh   16
#define HSd   64
#define BT    (Bb*Tt)          // 4096

// Scratch (device globals: no allocation allowed)
__device__ float g_P [QLd*KVL];
__device__ float g_M [Cc*KVL];
__device__ float g_N [NHh*QLd*KVL];
__device__ float g_R [Cc*KVL];
__device__ float g_Aq[BT*QLd];
__device__ float g_ql[NHh*BT*KVL];
__device__ float g_ct[NHh*BT*KVL];

// ===========================================================================
// SIMT tiled GEMM (unchanged from R1 — keeps c_kv/y in pure fp32)
// ===========================================================================
template<int MODE>
__global__ __launch_bounds__(256)
void gemm_kernel(const float* __restrict__ A, const float* __restrict__ B,
                 float* __restrict__ C, int M, int N, int K, int ldc,
                 long sA, long sB, long sC)
{
    constexpr int BM = 64, BN = 64, BK = 16;
    __shared__ float As[BK][BM + 1];
    __shared__ float Bs[BK][BN + 1];

    const int bz = blockIdx.z;
    A += (long)bz * sA;  B += (long)bz * sB;  C += (long)bz * sC;

    const int m0 = blockIdx.x * BM, n0 = blockIdx.y * BN;
    const int t  = threadIdx.x;
    const int ty = t >> 4, tx = t & 15;

    float acc[4][4] = {};

    for (int k0 = 0; k0 < K; k0 += BK) {
        #pragma unroll
        for (int i = 0; i < 4; i++) {
            int idx = t + i * 256;
            if (MODE == 2) { int am = idx & 63, ak = idx >> 6;
                As[ak][am] = A[(long)(k0 + ak) * M + m0 + am];
            } else {         int ak = idx & 15, am = idx >> 4;
                As[ak][am] = A[(long)(m0 + am) * K + k0 + ak]; }
        }
        #pragma unroll
        for (int i = 0; i < 4; i++) {
            int idx = t + i * 256;
            if (MODE == 1) { int bk = idx & 15, bn = idx >> 4;
                Bs[bk][bn] = B[(long)(n0 + bn) * K + k0 + bk];
            } else {         int bn = idx & 63, bk = idx >> 6;
                Bs[bk][bn] = B[(long)(k0 + bk) * N + n0 + bn]; }
        }
        __syncthreads();
        #pragma unroll
        for (int kk = 0; kk < BK; kk++) {
            float a[4], b[4];
            #pragma unroll
            for (int i = 0; i < 4; i++) a[i] = As[kk][ty * 4 + i];
            #pragma unroll
            for (int j = 0; j < 4; j++) b[j] = Bs[kk][tx * 4 + j];
            #pragma unroll
            for (int i = 0; i < 4; i++)
                #pragma unroll
                for (int j = 0; j < 4; j++) acc[i][j] += a[i] * b[j];
        }
        __syncthreads();
    }
    #pragma unroll
    for (int i = 0; i < 4; i++)
        #pragma unroll
        for (int j = 0; j < 4; j++)
            C[(long)(m0 + ty * 4 + i) * ldc + n0 + tx * 4 + j] = acc[i][j];
}

// ===========================================================================
// mma.sync tf32 flash attention (sm_80+ HMMA path — works on sm_103 target).
// CTA: 128 queries of one (b,h). Key tiles of 64. 8 warps x 16 query rows.
// S and O live in registers (m16n8k8 C-fragment layout). Softmax quad-local.
// ===========================================================================
#define QS_OFF  0
#define QS_LD   132
#define K1_OFF  16896          // K copy for S-phase  [key][d], stride 132
#define K1_LD   132
#define K2_OFF  25344          // K copy for PV-phase [key][d], stride 136
#define K2_LD   136
#define PS_OFF  34048          // per-warp P tiles [16][68]
#define PS_LD   68
#define ATT_SMEM_WORDS 42752   // 171008 bytes

__device__ __forceinline__ uint32_t f2tf(float f) {
    uint32_t u;
    asm("cvt.rna.tf32.f32 %0, %1;" : "=r"(u) : "f"(f));
    return u;
}

__device__ __forceinline__ void mma_tf32(float* d, const uint32_t* a, const uint32_t* b) {
    asm volatile(
        "mma.sync.aligned.m16n8k8.row.col.f32.tf32.tf32.f32 "
        "{%0,%1,%2,%3}, {%4,%5,%6,%7}, {%8,%9}, {%0,%1,%2,%3};"
        : "+f"(d[0]), "+f"(d[1]), "+f"(d[2]), "+f"(d[3])
        : "r"(a[0]), "r"(a[1]), "r"(a[2]), "r"(a[3]), "r"(b[0]), "r"(b[1]));
}

__global__ __launch_bounds__(256, 1)
void attn_mma_kernel(const float* __restrict__ ql, const float* __restrict__ ckv,
                     float* __restrict__ ctx)
{
    extern __shared__ uint32_t smu[];

    const int t   = threadIdx.x;
    const int w   = t >> 5;            // warp 0..7
    const int lid = t & 31;
    const int g   = lid >> 2;          // group id (row within 16-row warp tile)
    const int tid = lid & 3;           // thread-in-group

    const int qt = 15 - blockIdx.x;    // heavy tiles first
    const int bh = blockIdx.y;
    const int b  = bh >> 4, h = bh & 15;
    const long qbase = ((long)h * BT + (long)b * Tt + (long)qt * 128) * 128;
    const long kbase = (long)b * Tt * 128;

    // --- load Q tile (prescaled by 1/sqrt(64)=0.125, tf32-rounded) ---
    {
        const float* qs = ql + qbase;
        #pragma unroll
        for (int i = 0; i < 16; i++) {
            int idx = t + i * 256;
            int r = idx >> 5, d = (idx & 31) * 4;
            float4 v = *(const float4*)(qs + (long)r * 128 + d);
            uint4 u;
            u.x = f2tf(v.x * 0.125f); u.y = f2tf(v.y * 0.125f);
            u.z = f2tf(v.z * 0.125f); u.w = f2tf(v.w * 0.125f);
            *(uint4*)(smu + QS_OFF + r * QS_LD + d) = u;
        }
    }

    float oacc[16][4];
    #pragma unroll
    for (int nb = 0; nb < 16; nb++)
        #pragma unroll
        for (int j = 0; j < 4; j++) oacc[nb][j] = 0.f;

    float m_run[2] = { -1e30f, -1e30f };
    float l_run[2] = { 0.f, 0.f };

    const int row0 = qt * 128 + 16 * w + g;     // global query rows for this thread
    const int ktmax = 2 * qt + 2;
    const uint32_t* Ps = smu + PS_OFF + w * (16 * PS_LD);
    uint32_t* PsW = (uint32_t*)Ps;

    for (int kt = 0; kt < ktmax; kt++) {
        __syncthreads();   // previous PV done before K overwrite (also covers Q store on iter 0)
        {
            const float* ks = ckv + kbase + (long)kt * 64 * 128;
            #pragma unroll
            for (int i = 0; i < 8; i++) {
                int idx = t + i * 256;
                int s = idx >> 5, d = (idx & 31) * 4;
                float4 v = *(const float4*)(ks + (long)s * 128 + d);
                uint4 u;
                u.x = f2tf(v.x); u.y = f2tf(v.y); u.z = f2tf(v.z); u.w = f2tf(v.w);
                *(uint4*)(smu + K1_OFF + s * K1_LD + d) = u;
                *(uint4*)(smu + K2_OFF + s * K2_LD + d) = u;
            }
        }
        __syncthreads();

        // ---- S = Q K^T (prescaled): 16 k-steps over d, 8 n-blocks over keys ----
        float sacc[8][4];
        #pragma unroll
        for (int nb = 0; nb < 8; nb++)
            #pragma unroll
            for (int j = 0; j < 4; j++) sacc[nb][j] = 0.f;

        #pragma unroll
        for (int ks = 0; ks < 16; ks++) {
            uint32_t af[4];
            const int d0 = 8 * ks + tid;
            af[0] = smu[QS_OFF + (16 * w + g    ) * QS_LD + d0    ];
            af[1] = smu[QS_OFF + (16 * w + g + 8) * QS_LD + d0    ];
            af[2] = smu[QS_OFF + (16 * w + g    ) * QS_LD + d0 + 4];
            af[3] = smu[QS_OFF + (16 * w + g + 8) * QS_LD + d0 + 4];
            #pragma unroll
            for (int nb = 0; nb < 8; nb++) {
                uint32_t bf[2];
                bf[0] = smu[K1_OFF + (8 * nb + g) * K1_LD + d0    ];
                bf[1] = smu[K1_OFF + (8 * nb + g) * K1_LD + d0 + 4];
                mma_tf32(sacc[nb], af, bf);
            }
        }

        // ---- causal mask (only tiles overlapping the diagonal) ----
        if (64 * kt + 63 > row0) {
            #pragma unroll
            for (int nb = 0; nb < 8; nb++)
                #pragma unroll
                for (int j = 0; j < 2; j++) {
                    int col = 64 * kt + 8 * nb + 2 * tid + j;
                    if (col > row0)     sacc[nb][j]     = -1e30f;
                    if (col > row0 + 8) sacc[nb][2 + j] = -1e30f;
                }
        }

        // ---- online softmax (rows g and g+8; quad-local reductions) ----
        #pragma unroll
        for (int hh = 0; hh < 2; hh++) {
            float mt = -1e30f;
            #pragma unroll
            for (int nb = 0; nb < 8; nb++)
                mt = fmaxf(mt, fmaxf(sacc[nb][2 * hh], sacc[nb][2 * hh + 1]));
            mt = fmaxf(mt, __shfl_xor_sync(0xffffffffu, mt, 1));
            mt = fmaxf(mt, __shfl_xor_sync(0xffffffffu, mt, 2));

            const float mn = fmaxf(m_run[hh], mt);
            const float sc = __expf(m_run[hh] - mn);
            float ls = 0.f;
            #pragma unroll
            for (int nb = 0; nb < 8; nb++) {
                float p0 = __expf(sacc[nb][2 * hh]     - mn);
                float p1 = __expf(sacc[nb][2 * hh + 1] - mn);
                ls += p0 + p1;
                uint2 u; u.x = f2tf(p0); u.y = f2tf(p1);
                *(uint2*)(PsW + (g + 8 * hh) * PS_LD + 8 * nb + 2 * tid) = u;
            }
            ls += __shfl_xor_sync(0xffffffffu, ls, 1);
            ls += __shfl_xor_sync(0xffffffffu, ls, 2);
            l_run[hh] = l_run[hh] * sc + ls;
            m_run[hh] = mn;
            #pragma unroll
            for (int nb = 0; nb < 16; nb++) {
                oacc[nb][2 * hh]     *= sc;
                oacc[nb][2 * hh + 1] *= sc;
            }
        }
        __syncwarp();

        // ---- O += P @ Ktile : 8 k-steps over keys, 16 n-blocks over d ----
        #pragma unroll
        for (int ks = 0; ks < 8; ks++) {
            uint32_t af[4];
            const int s0 = 8 * ks + tid;
            af[0] = Ps[(g    ) * PS_LD + s0    ];
            af[1] = Ps[(g + 8) * PS_LD + s0    ];
            af[2] = Ps[(g    ) * PS_LD + s0 + 4];
            af[3] = Ps[(g + 8) * PS_LD + s0 + 4];
            #pragma unroll
            for (int nb = 0; nb < 16; nb++) {
                uint32_t bf[2];
                bf[0] = smu[K2_OFF + (s0    ) * K2_LD + 8 * nb + g];
                bf[1] = smu[K2_OFF + (s0 + 4) * K2_LD + 8 * nb + g];
                mma_tf32(oacc[nb], af, bf);
            }
        }
    }

    // ---- epilogue: ctx = O / l ----
    const float inv0 = 1.f / l_run[0];
    const float inv1 = 1.f / l_run[1];
    float* dst0 = ctx + qbase + (long)(16 * w + g    ) * 128;
    float* dst1 = ctx + qbase + (long)(16 * w + g + 8) * 128;
    #pragma unroll
    for (int nb = 0; nb < 16; nb++) {
        const int d0 = 8 * nb + 2 * tid;
        float2 v0 = { oacc[nb][0] * inv0, oacc[nb][1] * inv0 };
        float2 v1 = { oacc[nb][2] * inv1, oacc[nb][3] * inv1 };
        *(float2*)(dst0 + d0) = v0;
        *(float2*)(dst1 + d0) = v1;
    }
}

// ===========================================================================
extern "C" void kernel_launch(void* const* d_in, const int* in_sizes, int n_in,
                              void* d_out, int out_size)
{
    const float* x     = (const float*)d_in[0];
    const float* W_dq  = (const float*)d_in[1];
    const float* W_uq  = (const float*)d_in[2];
    const float* W_dkv = (const float*)d_in[3];
    const float* W_uk  = (const float*)d_in[4];
    const float* W_uv  = (const float*)d_in[5];
    const float* W_o   = (const float*)d_in[6];

    float* y   = (float*)d_out;
    float* ckv = y + (long)BT * Cc;

    float *P, *Mm, *Nw, *R, *Aq, *QLp, *CT;
    cudaGetSymbolAddress((void**)&P,  g_P);
    cudaGetSymbolAddress((void**)&Mm, g_M);
    cudaGetSymbolAddress((void**)&Nw, g_N);
    cudaGetSymbolAddress((void**)&R,  g_R);
    cudaGetSymbolAddress((void**)&Aq, g_Aq);
    cudaGetSymbolAddress((void**)&QLp, g_ql);
    cudaGetSymbolAddress((void**)&CT, g_ct);

    dim3 blk(256);

    gemm_kernel<2><<<dim3(2, 2, 1), blk>>>(W_uq, W_uk, P, 128, 128, 1024, 128, 0, 0, 0);
    gemm_kernel<2><<<dim3(16, 2, 1), blk>>>(W_dq, P, Mm, 1024, 128, 128, 128, 0, 0, 0);
    gemm_kernel<2><<<dim3(2, 2, 16), blk>>>(W_uq, Mm, Nw, 128, 128, 64, 128,
                                            64 * 128, 64 * 128, 128 * 128);
    gemm_kernel<0><<<dim3(16, 2, 1), blk>>>(W_o, W_uv, R, 1024, 128, 1024, 128, 0, 0, 0);
    gemm_kernel<1><<<dim3(64, 2, 1), blk>>>(x, W_dq, Aq, BT, 128, 1024, 128, 0, 0, 0);
    gemm_kernel<1><<<dim3(64, 2, 1), blk>>>(x, W_dkv, ckv, BT, 128, 1024, 128, 0, 0, 0);
    gemm_kernel<0><<<dim3(64, 2, 16), blk>>>(Aq, Nw, QLp, BT, 128, 128, 128,
                                             0, 128 * 128, (long)BT * 128);

    cudaFuncSetAttribute(attn_mma_kernel, cudaFuncAttributeMaxDynamicSharedMemorySize,
                         ATT_SMEM_WORDS * 4);
    attn_mma_kernel<<<dim3(16, 32, 1), blk, ATT_SMEM_WORDS * 4>>>(QLp, ckv, CT);

    gemm_kernel<1><<<dim3(64, 1, 16), blk>>>(CT, R, y, BT, 64, 128, 1024,
                                             (long)BT * 128, 64 * 128, 64);
}

// round 4
// speedup vs baseline: 4.9838x; 1.3307x over previous
#include <cuda_runtime.h>
#include <cstdint>

// Problem constants (fixed by setup_inputs)
#define Bb    2
#define Tt    2048
#define Cc    1024
#define QLd   128
#define KVL   128
#define NHh   16
#define HSd   64
#define BT    (Bb*Tt)          // 4096

// Scratch (device globals: no allocation allowed)
__device__ float g_P [QLd*KVL];          // W_uq^T @ W_uk          (128,128)
__device__ float g_Mt[KVL*Cc];           // (W_dq^T @ P)^T         (128,1024)
__device__ float g_R [Cc*KVL];           // W_o @ W_uv             (1024,128)
__device__ float g_Aq[BT*QLd];           // x @ W_dq^T             (4096,128)
__device__ float g_qf[BT*Cc];            // Aq @ W_uq^T            (4096,1024)
__device__ float g_ql[NHh*BT*KVL];       // latent queries         (16,4096,128)
__device__ float g_ct[NHh*BT*KVL];       // latent context         (16,4096,128)

__device__ __forceinline__ uint32_t f2tf(float f) {
    uint32_t u;
    asm("cvt.rna.tf32.f32 %0, %1;" : "=r"(u) : "f"(f));
    return u;
}
__device__ __forceinline__ void mma_tf32(float* d, const uint32_t* a, const uint32_t* b) {
    asm volatile(
        "mma.sync.aligned.m16n8k8.row.col.f32.tf32.tf32.f32 "
        "{%0,%1,%2,%3}, {%4,%5,%6,%7}, {%8,%9}, {%0,%1,%2,%3};"
        : "+f"(d[0]), "+f"(d[1]), "+f"(d[2]), "+f"(d[3])
        : "r"(a[0]), "r"(a[1]), "r"(a[2]), "r"(a[3]), "r"(b[0]), "r"(b[1]));
}

// ===========================================================================
// tf32 tensor-core GEMM.  C[m,n] = sum_k A[m,k] * opB.
//   NN=false: B is [n][k] row-major (NT form, natural for mma row.col)
//   NN=true : B is [k][n] row-major (transposed into smem on load)
// COMP: 2-term tf32 error compensation (hi*hi + hi*lo + lo*hi) ~ fp32.
// Fused second operand: blocks with by >= nb1 use B2/C2 (n0 rebased).
// BM=128, BK=16, 256 threads; warps 4(m) x 2(n); warp tile 32 x BN/2.
// ===========================================================================
template<int BN, bool NN, bool COMP>
__global__ __launch_bounds__(256)
void tgemm(const float* __restrict__ A, const float* __restrict__ B,
           float* __restrict__ C, const float* __restrict__ B2,
           float* __restrict__ C2, int K,
           int lda, int ldb, int ldc, long sA, long sB, long sC, int nb1)
{
    constexpr int BM = 128, AW = BM * 20, BW = BN * 20;
    constexpr int NF = BN / 16;                 // n-frags per warp
    extern __shared__ uint32_t sh[];
    uint32_t* Ah = sh;
    uint32_t* Bh = sh + AW;
    uint32_t* Al = sh + AW + BW;                // COMP only
    uint32_t* Bl = sh + 2 * AW + BW;            // COMP only

    const int z = blockIdx.z;
    A += (long)z * sA;
    const float* Bp = B;  float* Cp = C;
    int by = blockIdx.y;
    if (by >= nb1) { Bp = B2; Cp = C2; by -= nb1; }
    Bp += (long)z * sB;  Cp += (long)z * sC;

    const int m0 = blockIdx.x * BM, n0 = by * BN;
    const int t = threadIdx.x;
    const int wid = t >> 5, g = (t & 31) >> 2, tid = t & 3;
    const int wm = wid >> 1, wn = wid & 1;

    float acc[2][NF][4];
    #pragma unroll
    for (int i = 0; i < 2; i++)
        #pragma unroll
        for (int j = 0; j < NF; j++)
            #pragma unroll
            for (int q = 0; q < 4; q++) acc[i][j][q] = 0.f;

    for (int k0 = 0; k0 < K; k0 += 16) {
        // ---- A tile: BM x 16 ----
        #pragma unroll
        for (int i = 0; i < 2; i++) {
            int idx = t + i * 256;
            int r = idx >> 2, cg = (idx & 3) * 4;
            float4 v = *(const float4*)(A + (long)(m0 + r) * lda + k0 + cg);
            uint4 h; h.x = f2tf(v.x); h.y = f2tf(v.y); h.z = f2tf(v.z); h.w = f2tf(v.w);
            *(uint4*)(Ah + r * 20 + cg) = h;
            if (COMP) {
                uint4 l;
                l.x = f2tf(v.x - __uint_as_float(h.x));
                l.y = f2tf(v.y - __uint_as_float(h.y));
                l.z = f2tf(v.z - __uint_as_float(h.z));
                l.w = f2tf(v.w - __uint_as_float(h.w));
                *(uint4*)(Al + r * 20 + cg) = l;
            }
        }
        // ---- B tile ----
        if (!NN) {                                   // B[n][k], BN x 16
            #pragma unroll
            for (int i = 0; i < BN / 64; i++) {
                int idx = t + i * 256;
                int r = idx >> 2, cg = (idx & 3) * 4;
                float4 v = *(const float4*)(Bp + (long)(n0 + r) * ldb + k0 + cg);
                uint4 h; h.x = f2tf(v.x); h.y = f2tf(v.y); h.z = f2tf(v.z); h.w = f2tf(v.w);
                *(uint4*)(Bh + r * 20 + cg) = h;
                if (COMP) {
                    uint4 l;
                    l.x = f2tf(v.x - __uint_as_float(h.x));
                    l.y = f2tf(v.y - __uint_as_float(h.y));
                    l.z = f2tf(v.z - __uint_as_float(h.z));
                    l.w = f2tf(v.w - __uint_as_float(h.w));
                    *(uint4*)(Bl + r * 20 + cg) = l;
                }
            }
        } else {                                     // B[k][n] -> transpose to smem
            #pragma unroll
            for (int i = 0; i < BN / 64; i++) {
                int idx = t + i * 256;
                int kr = idx >> (BN == 64 ? 4 : 5);
                int nn = (idx & (BN / 4 - 1)) * 4;
                float4 v = *(const float4*)(Bp + (long)(k0 + kr) * ldb + n0 + nn);
                Bh[(nn + 0) * 20 + kr] = f2tf(v.x);
                Bh[(nn + 1) * 20 + kr] = f2tf(v.y);
                Bh[(nn + 2) * 20 + kr] = f2tf(v.z);
                Bh[(nn + 3) * 20 + kr] = f2tf(v.w);
            }
        }
        __syncthreads();

        #pragma unroll
        for (int s = 0; s < 2; s++) {
            const int kk = 8 * s + tid;
            uint32_t ah[2][4], al[2][4];
            #pragma unroll
            for (int mf = 0; mf < 2; mf++) {
                int r = wm * 32 + 16 * mf + g;
                ah[mf][0] = Ah[r * 20 + kk];       ah[mf][1] = Ah[(r + 8) * 20 + kk];
                ah[mf][2] = Ah[r * 20 + kk + 4];   ah[mf][3] = Ah[(r + 8) * 20 + kk + 4];
                if (COMP) {
                    al[mf][0] = Al[r * 20 + kk];     al[mf][1] = Al[(r + 8) * 20 + kk];
                    al[mf][2] = Al[r * 20 + kk + 4]; al[mf][3] = Al[(r + 8) * 20 + kk + 4];
                }
            }
            uint32_t bh[NF][2], bl[NF][2];
            #pragma unroll
            for (int nf = 0; nf < NF; nf++) {
                int n = wn * (BN / 2) + 8 * nf + g;
                bh[nf][0] = Bh[n * 20 + kk];  bh[nf][1] = Bh[n * 20 + kk + 4];
                if (COMP) { bl[nf][0] = Bl[n * 20 + kk]; bl[nf][1] = Bl[n * 20 + kk + 4]; }
            }
            #pragma unroll
            for (int mf = 0; mf < 2; mf++)
                #pragma unroll
                for (int nf = 0; nf < NF; nf++) {
                    mma_tf32(acc[mf][nf], ah[mf], bh[nf]);
                    if (COMP) {
                        mma_tf32(acc[mf][nf], ah[mf], bl[nf]);
                        mma_tf32(acc[mf][nf], al[mf], bh[nf]);
                    }
                }
        }
        __syncthreads();
    }

    #pragma unroll
    for (int mf = 0; mf < 2; mf++) {
        const int r0 = m0 + wm * 32 + 16 * mf + g;
        #pragma unroll
        for (int nf = 0; nf < NF; nf++) {
            const int c = n0 + wn * (BN / 2) + 8 * nf + 2 * tid;
            *(float2*)(Cp + (long)r0 * ldc + c)       = make_float2(acc[mf][nf][0], acc[mf][nf][1]);
            *(float2*)(Cp + (long)(r0 + 8) * ldc + c) = make_float2(acc[mf][nf][2], acc[mf][nf][3]);
        }
    }
}

// ===========================================================================
// Tiny precompute kernels (latency-optimized SIMT, fp32-exact)
// ===========================================================================
// P[i,j] = sum_c W_uq[c,i] * W_uk[c,j]
__global__ __launch_bounds__(128)
void pk_kernel(const float* __restrict__ W_uq, const float* __restrict__ W_uk,
               float* __restrict__ P)
{
    const int i = blockIdx.x, j = threadIdx.x;
    float s = 0.f;
    #pragma unroll 8
    for (int c = 0; c < 1024; c++)
        s += W_uq[c * 128 + i] * W_uk[c * 128 + j];
    P[i * 128 + j] = s;
}
// Mt[j,c] = sum_i W_dq[i,c] * P[i,j]   (Mt = (W_dq^T @ P)^T, 128 x 1024)
__global__ __launch_bounds__(128)
void mt_kernel(const float* __restrict__ W_dq, const float* __restrict__ P,
               float* __restrict__ Mt)
{
    const int c = blockIdx.x * 128 + threadIdx.x;
    const int j = blockIdx.y;
    float s = 0.f;
    #pragma unroll 8
    for (int i = 0; i < 128; i++)
        s += W_dq[i * 1024 + c] * P[i * 128 + j];
    Mt[j * 1024 + c] = s;
}

// ===========================================================================
// mma.sync tf32 flash attention (unchanged from R3)
// ===========================================================================
#define QS_OFF  0
#define QS_LD   132
#define K1_OFF  16896
#define K1_LD   132
#define K2_OFF  25344
#define K2_LD   136
#define PS_OFF  34048
#define PS_LD   68
#define ATT_SMEM_WORDS 42752

__global__ __launch_bounds__(256, 1)
void attn_mma_kernel(const float* __restrict__ ql, const float* __restrict__ ckv,
                     float* __restrict__ ctx)
{
    extern __shared__ uint32_t smu[];

    const int t   = threadIdx.x;
    const int w   = t >> 5;
    const int lid = t & 31;
    const int g   = lid >> 2;
    const int tid = lid & 3;

    const int qt = 15 - blockIdx.x;
    const int bh = blockIdx.y;
    const int b  = bh >> 4, h = bh & 15;
    const long qbase = ((long)h * BT + (long)b * Tt + (long)qt * 128) * 128;
    const long kbase = (long)b * Tt * 128;

    {
        const float* qs = ql + qbase;
        #pragma unroll
        for (int i = 0; i < 16; i++) {
            int idx = t + i * 256;
            int r = idx >> 5, d = (idx & 31) * 4;
            float4 v = *(const float4*)(qs + (long)r * 128 + d);
            uint4 u;
            u.x = f2tf(v.x * 0.125f); u.y = f2tf(v.y * 0.125f);
            u.z = f2tf(v.z * 0.125f); u.w = f2tf(v.w * 0.125f);
            *(uint4*)(smu + QS_OFF + r * QS_LD + d) = u;
        }
    }

    float oacc[16][4];
    #pragma unroll
    for (int nb = 0; nb < 16; nb++)
        #pragma unroll
        for (int j = 0; j < 4; j++) oacc[nb][j] = 0.f;

    float m_run[2] = { -1e30f, -1e30f };
    float l_run[2] = { 0.f, 0.f };

    const int row0 = qt * 128 + 16 * w + g;
    const int ktmax = 2 * qt + 2;
    const uint32_t* Ps = smu + PS_OFF + w * (16 * PS_LD);
    uint32_t* PsW = (uint32_t*)Ps;

    for (int kt = 0; kt < ktmax; kt++) {
        __syncthreads();
        {
            const float* ks = ckv + kbase + (long)kt * 64 * 128;
            #pragma unroll
            for (int i = 0; i < 8; i++) {
                int idx = t + i * 256;
                int s = idx >> 5, d = (idx & 31) * 4;
                float4 v = *(const float4*)(ks + (long)s * 128 + d);
                uint4 u;
                u.x = f2tf(v.x); u.y = f2tf(v.y); u.z = f2tf(v.z); u.w = f2tf(v.w);
                *(uint4*)(smu + K1_OFF + s * K1_LD + d) = u;
                *(uint4*)(smu + K2_OFF + s * K2_LD + d) = u;
            }
        }
        __syncthreads();

        float sacc[8][4];
        #pragma unroll
        for (int nb = 0; nb < 8; nb++)
            #pragma unroll
            for (int j = 0; j < 4; j++) sacc[nb][j] = 0.f;

        #pragma unroll
        for (int ks = 0; ks < 16; ks++) {
            uint32_t af[4];
            const int d0 = 8 * ks + tid;
            af[0] = smu[QS_OFF + (16 * w + g    ) * QS_LD + d0    ];
            af[1] = smu[QS_OFF + (16 * w + g + 8) * QS_LD + d0    ];
            af[2] = smu[QS_OFF + (16 * w + g    ) * QS_LD + d0 + 4];
            af[3] = smu[QS_OFF + (16 * w + g + 8) * QS_LD + d0 + 4];
            #pragma unroll
            for (int nb = 0; nb < 8; nb++) {
                uint32_t bf[2];
                bf[0] = smu[K1_OFF + (8 * nb + g) * K1_LD + d0    ];
                bf[1] = smu[K1_OFF + (8 * nb + g) * K1_LD + d0 + 4];
                mma_tf32(sacc[nb], af, bf);
            }
        }

        if (64 * kt + 63 > row0) {
            #pragma unroll
            for (int nb = 0; nb < 8; nb++)
                #pragma unroll
                for (int j = 0; j < 2; j++) {
                    int col = 64 * kt + 8 * nb + 2 * tid + j;
                    if (col > row0)     sacc[nb][j]     = -1e30f;
                    if (col > row0 + 8) sacc[nb][2 + j] = -1e30f;
                }
        }

        #pragma unroll
        for (int hh = 0; hh < 2; hh++) {
            float mt = -1e30f;
            #pragma unroll
            for (int nb = 0; nb < 8; nb++)
                mt = fmaxf(mt, fmaxf(sacc[nb][2 * hh], sacc[nb][2 * hh + 1]));
            mt = fmaxf(mt, __shfl_xor_sync(0xffffffffu, mt, 1));
            mt = fmaxf(mt, __shfl_xor_sync(0xffffffffu, mt, 2));

            const float mn = fmaxf(m_run[hh], mt);
            const float sc = __expf(m_run[hh] - mn);
            float ls = 0.f;
            #pragma unroll
            for (int nb = 0; nb < 8; nb++) {
                float p0 = __expf(sacc[nb][2 * hh]     - mn);
                float p1 = __expf(sacc[nb][2 * hh + 1] - mn);
                ls += p0 + p1;
                uint2 u; u.x = f2tf(p0); u.y = f2tf(p1);
                *(uint2*)(PsW + (g + 8 * hh) * PS_LD + 8 * nb + 2 * tid) = u;
            }
            ls += __shfl_xor_sync(0xffffffffu, ls, 1);
            ls += __shfl_xor_sync(0xffffffffu, ls, 2);
            l_run[hh] = l_run[hh] * sc + ls;
            m_run[hh] = mn;
            #pragma unroll
            for (int nb = 0; nb < 16; nb++) {
                oacc[nb][2 * hh]     *= sc;
                oacc[nb][2 * hh + 1] *= sc;
            }
        }
        __syncwarp();

        #pragma unroll
        for (int ks = 0; ks < 8; ks++) {
            uint32_t af[4];
            const int s0 = 8 * ks + tid;
            af[0] = Ps[(g    ) * PS_LD + s0    ];
            af[1] = Ps[(g + 8) * PS_LD + s0    ];
            af[2] = Ps[(g    ) * PS_LD + s0 + 4];
            af[3] = Ps[(g + 8) * PS_LD + s0 + 4];
            #pragma unroll
            for (int nb = 0; nb < 16; nb++) {
                uint32_t bf[2];
                bf[0] = smu[K2_OFF + (s0    ) * K2_LD + 8 * nb + g];
                bf[1] = smu[K2_OFF + (s0 + 4) * K2_LD + 8 * nb + g];
                mma_tf32(oacc[nb], af, bf);
            }
        }
    }

    const float inv0 = 1.f / l_run[0];
    const float inv1 = 1.f / l_run[1];
    float* dst0 = ctx + qbase + (long)(16 * w + g    ) * 128;
    float* dst1 = ctx + qbase + (long)(16 * w + g + 8) * 128;
    #pragma unroll
    for (int nb = 0; nb < 16; nb++) {
        const int d0 = 8 * nb + 2 * tid;
        *(float2*)(dst0 + d0) = make_float2(oacc[nb][0] * inv0, oacc[nb][1] * inv0);
        *(float2*)(dst1 + d0) = make_float2(oacc[nb][2] * inv1, oacc[nb][3] * inv1);
    }
}

// ===========================================================================
extern "C" void kernel_launch(void* const* d_in, const int* in_sizes, int n_in,
                              void* d_out, int out_size)
{
    const float* x     = (const float*)d_in[0];
    const float* W_dq  = (const float*)d_in[1];
    const float* W_uq  = (const float*)d_in[2];
    const float* W_dkv = (const float*)d_in[3];
    const float* W_uk  = (const float*)d_in[4];
    const float* W_uv  = (const float*)d_in[5];
    const float* W_o   = (const float*)d_in[6];

    float* y   = (float*)d_out;
    float* ckv = y + (long)BT * Cc;

    float *P, *Mt, *R, *Aq, *QF, *QLp, *CT;
    cudaGetSymbolAddress((void**)&P,  g_P);
    cudaGetSymbolAddress((void**)&Mt, g_Mt);
    cudaGetSymbolAddress((void**)&R,  g_R);
    cudaGetSymbolAddress((void**)&Aq, g_Aq);
    cudaGetSymbolAddress((void**)&QF, g_qf);
    cudaGetSymbolAddress((void**)&QLp, g_ql);
    cudaGetSymbolAddress((void**)&CT, g_ct);

    const int NONE = 1 << 30;
    const size_t S64   = (128 * 20 + 64 * 20) * 4;            // BN=64 plain
    const size_t S128  = (128 * 20 + 128 * 20) * 4;           // BN=128 plain
    const size_t S64C  = 2 * S64;                             // BN=64 COMP

    // P = W_uq^T @ W_uk ; Mt = (W_dq^T @ P)^T
    pk_kernel<<<128, 128>>>(W_uq, W_uk, P);
    mt_kernel<<<dim3(8, 128), 128>>>(W_dq, P, Mt);

    // Fused: Aq = x @ W_dq^T  |  ckv = x @ W_dkv^T   (compensated tf32 ~ fp32)
    tgemm<64, false, true><<<dim3(32, 4), 256, S64C>>>(
        x, W_dq, Aq, W_dkv, ckv, 1024, 1024, 1024, 128, 0, 0, 0, 2);

    // q_full = Aq @ W_uq^T          (4096 x 1024, K=128)
    tgemm<128, false, false><<<dim3(32, 8), 256, S128>>>(
        Aq, W_uq, QF, nullptr, nullptr, 128, 128, 128, 1024, 0, 0, 0, NONE);

    // ql[h] = q_full[:, h*64:] @ Mt[:, h*64:]^T    (batched 16, K=64)
    tgemm<128, false, false><<<dim3(32, 1, 16), 256, S128>>>(
        QF, Mt, QLp, nullptr, nullptr, 64, 1024, 1024, 128,
        64, 64, (long)BT * 128, NONE);

    // R = W_o @ W_uv                (1024 x 128, K=1024, NN)
    tgemm<64, true, false><<<dim3(8, 2), 256, S64>>>(
        W_o, W_uv, R, nullptr, nullptr, 1024, 1024, 128, 128, 0, 0, 0, NONE);

    // flash attention -> ctx
    cudaFuncSetAttribute(attn_mma_kernel, cudaFuncAttributeMaxDynamicSharedMemorySize,
                         ATT_SMEM_WORDS * 4);
    attn_mma_kernel<<<dim3(16, 32, 1), 256, ATT_SMEM_WORDS * 4>>>(QLp, ckv, CT);

    // y[:, h*64:] = ctx[h] @ R[h*64:, :]^T   (batched 16, K=128, N=64)
    tgemm<64, false, false><<<dim3(32, 1, 16), 256, S64>>>(
        CT, R, y, nullptr, nullptr, 128, 128, 128, 1024,
        (long)BT * 128, 64 * 128, 64, NONE);
}